// round 6
// baseline (speedup 1.0000x reference)
#include <cuda_runtime.h>
#include <cuda_bf16.h>

// DCTPolicy: out = [coeffs (3*4096*4096 f32), log_prob, entropy]
//
// Single fused kernel. Each CTA owns an 8-row x 2048-col output tile
// (= 256 consecutive 8x8 blocks = 4096 CONTIGUOUS params per array):
//   Phase 1: coalesced float4 loads of mean/log_std/eps, compute sample,
//            stage into smem (transposed, padded stride), accumulate the
//            two reductions in registers.
//   Phase 2: coalesced float4 STREAMING stores (st.global.cs) of the full
//            tile, gathering kept coefficients from smem via the constant
//            zig-zag rank table. Evict-first keeps the 201MB of dead write
//            data from thrashing L2 against the param loads.
//   Tail:    per-CTA partials -> global slots; last CTA reduces in double,
//            writes the two scalars, resets the counter (graph-replay safe).
//
// __launch_bounds__(256, 8) forces <=32 regs -> 8 CTAs/SM (64 warps), fixing
// the register-limited 70% occupancy seen at 40 regs (6 CTAs/SM).

#define CC    3
#define HH    4096
#define WW    4096
#define CHW   (CC * HH * WW)            // 50331648
#define NPAR  12582912                   // C * 512 * 512 * 16
#define NTILE 3072                       // C * 512 * 2 tiles (8 x 2048 each)
#define SMSTRIDE 258                     // 16 ranks * 258 floats (padded)

__device__ float g_p1[NTILE];            // per-CTA sum(eps^2)
__device__ float g_p2[NTILE];            // per-CTA sum(log_std)
__device__ int   g_done = 0;             // completion counter

// zigzag rank within 8x8 block for the first 16 coefficients; -1 = not kept.
__constant__ signed char RANK[64] = {
     0,  2,  3,  9, 10, -1, -1, -1,   // u=0
     1,  4,  8, 11, -1, -1, -1, -1,   // u=1
     5,  7, 12, -1, -1, -1, -1, -1,   // u=2
     6, 13, -1, -1, -1, -1, -1, -1,   // u=3
    14, -1, -1, -1, -1, -1, -1, -1,   // u=4
    15, -1, -1, -1, -1, -1, -1, -1,   // u=5
    -1, -1, -1, -1, -1, -1, -1, -1,   // u=6
    -1, -1, -1, -1, -1, -1, -1, -1    // u=7
};

__device__ __forceinline__ void stg_cs_v4(float* p, float x, float y, float z, float w)
{
    asm volatile("st.global.cs.v4.f32 [%0], {%1, %2, %3, %4};"
                 :: "l"(p), "f"(x), "f"(y), "f"(z), "f"(w) : "memory");
}

__global__ __launch_bounds__(256, 8)
void dct_tile_kernel(const float* __restrict__ mean,
                     const float* __restrict__ lstd,
                     const float* __restrict__ eps,
                     float* __restrict__ out, int out_size)
{
    __shared__ float sm[16 * SMSTRIDE];   // sm[rank*258 + blk], 16.5 KB

    const int tile = blockIdx.x;          // 0..3071
    const int c    = tile >> 10;          // tile / 1024
    const int rr   = tile & 1023;
    const int bh   = rr >> 1;             // block-row 0..511
    const int tw   = rr & 1;              // which 2048-col half
    const int tid  = threadIdx.x;

    // param base for this tile: ((c*512 + bh)*512 + tw*256) * 16 floats
    const int base = ((((c << 9) + bh) << 9) + (tw << 8)) << 4;
    const float4* m4 = (const float4*)(mean + base);
    const float4* l4 = (const float4*)(lstd + base);
    const float4* e4 = (const float4*)(eps  + base);

    float s1 = 0.f, s2 = 0.f;

    // ---- Phase 1: coalesced param load + sample + stage to smem ----
    #pragma unroll
    for (int k = 0; k < 4; k++) {
        int f = tid + (k << 8);           // float4 index, 0..1023
        float4 m = m4[f];
        float4 l = l4[f];
        float4 e = e4[f];
        float4 s;
        s.x = fmaf(__expf(l.x), e.x, m.x);
        s.y = fmaf(__expf(l.y), e.y, m.y);
        s.z = fmaf(__expf(l.z), e.z, m.z);
        s.w = fmaf(__expf(l.w), e.w, m.w);
        s1 = fmaf(e.x, e.x, s1); s1 = fmaf(e.y, e.y, s1);
        s1 = fmaf(e.z, e.z, s1); s1 = fmaf(e.w, e.w, s1);
        s2 += (l.x + l.y) + (l.z + l.w);
        int p = f << 2;                   // param index within tile
        // transposed, padded layout: conflict-free (banks 8a+b, all distinct)
        sm[((p + 0) & 15) * SMSTRIDE + ((p + 0) >> 4)] = s.x;
        sm[((p + 1) & 15) * SMSTRIDE + ((p + 1) >> 4)] = s.y;
        sm[((p + 2) & 15) * SMSTRIDE + ((p + 2) >> 4)] = s.z;
        sm[((p + 3) & 15) * SMSTRIDE + ((p + 3) >> 4)] = s.w;
    }
    __syncthreads();

    // ---- Phase 2: coalesced streaming tile store with smem gather ----
    const int rowbase = (c << 12) + (bh << 3);   // global row of u=0

    #pragma unroll
    for (int k = 0; k < 16; k++) {
        int f    = tid + (k << 8);        // 0..4095 (tile float4 index)
        int u    = f >> 9;                // row within tile, 0..7
        int col4 = f & 511;               // float4 col within tile
        int half = col4 & 1;              // v0 = 4*half
        int blk  = col4 >> 1;             // block within tile, 0..255
        int ri   = (u << 3) + (half << 2);
        int r0 = RANK[ri + 0];
        int r1 = RANK[ri + 1];
        int r2 = RANK[ri + 2];
        int r3 = RANK[ri + 3];
        float vx = (r0 >= 0) ? sm[r0 * SMSTRIDE + blk] : 0.f;
        float vy = (r1 >= 0) ? sm[r1 * SMSTRIDE + blk] : 0.f;
        float vz = (r2 >= 0) ? sm[r2 * SMSTRIDE + blk] : 0.f;
        float vw = (r3 >= 0) ? sm[r3 * SMSTRIDE + blk] : 0.f;
        int o = (rowbase + u) * 1024 + (tw << 9) + col4;
        stg_cs_v4(out + (o << 2), vx, vy, vz, vw);
    }

    // ---- Per-CTA reduction: warp shfl -> shared -> partial slot ----
    #pragma unroll
    for (int off = 16; off > 0; off >>= 1) {
        s1 += __shfl_down_sync(0xffffffffu, s1, off);
        s2 += __shfl_down_sync(0xffffffffu, s2, off);
    }
    __shared__ float sh1[8], sh2[8];
    __shared__ int is_last;
    int lane = tid & 31, wrp = tid >> 5;
    if (lane == 0) { sh1[wrp] = s1; sh2[wrp] = s2; }
    __syncthreads();
    if (tid == 0) {
        float t1 = 0.f, t2 = 0.f;
        #pragma unroll
        for (int i = 0; i < 8; i++) { t1 += sh1[i]; t2 += sh2[i]; }
        g_p1[tile] = t1;
        g_p2[tile] = t2;
        __threadfence();                     // make partials visible
        int old = atomicAdd(&g_done, 1);
        is_last = (old == NTILE - 1);
    }
    __syncthreads();

    // ---- Last CTA: final reduction over all 3072 partials ----
    if (is_last) {
        double t1 = 0.0, t2 = 0.0;
        for (int i = tid; i < NTILE; i += 256) {
            t1 += (double)g_p1[i];
            t2 += (double)g_p2[i];
        }
        #pragma unroll
        for (int off = 16; off > 0; off >>= 1) {
            t1 += __shfl_down_sync(0xffffffffu, t1, off);
            t2 += __shfl_down_sync(0xffffffffu, t2, off);
        }
        __shared__ double dh1[8], dh2[8];
        if (lane == 0) { dh1[wrp] = t1; dh2[wrp] = t2; }
        __syncthreads();
        if (tid == 0) {
            double S1 = 0.0, S2 = 0.0;
            #pragma unroll
            for (int i = 0; i < 8; i++) { S1 += dh1[i]; S2 += dh2[i]; }
            const double LOG2PI = 1.8378770664093454836;
            double lp  = -0.5 * (S1 + 2.0 * S2 + (double)NPAR * LOG2PI);
            double ent = (double)NPAR * 0.5 * (1.0 + LOG2PI) + S2;
            if (out_size >= CHW + 2) {
                out[CHW]     = (float)lp;
                out[CHW + 1] = (float)ent;
            }
            g_done = 0;                      // reset for next graph replay
        }
    }
}

extern "C" void kernel_launch(void* const* d_in, const int* in_sizes, int n_in,
                              void* d_out, int out_size)
{
    const float* mean = (const float*)d_in[0];
    const float* lstd = (const float*)d_in[1];
    const float* eps  = (const float*)d_in[2];
    // d_in[3] = flat_idx — unused; index map computed analytically.
    float* out = (float*)d_out;

    dct_tile_kernel<<<NTILE, 256>>>(mean, lstd, eps, out, out_size);
}

// round 7
// speedup vs baseline: 1.0133x; 1.0133x over previous
#include <cuda_runtime.h>
#include <cuda_bf16.h>

// DCTPolicy: out = [coeffs (3*4096*4096 f32), log_prob, entropy]
//
// Single fused kernel. Each CTA owns an 8-row x 2048-col output tile
// (= 256 consecutive 8x8 blocks = 4096 CONTIGUOUS params per array):
//   Phase 0: store the all-zero output rows (u=6,7 -> k=12..15) IMMEDIATELY.
//            They depend on nothing, and issuing them first overlaps 25% of
//            store traffic with the param-load phase (mixed HBM stream).
//   Phase 1: coalesced float4 loads of mean/log_std/eps, compute sample,
//            stage into smem (transposed, padded stride), accumulate the
//            two reductions in registers.
//   Phase 2: coalesced float4 stores of rows u=0..5, gathering kept
//            coefficients from smem via the constant zig-zag rank table.
//   Tail:    per-CTA partials -> global slots; last CTA reduces in double,
//            writes the two scalars, resets the counter (graph-replay safe).
//
// NOTE: st.global.cs was tried (R5) and REGRESSED (-2..-4us) — plain STG.128
// full-line writes already avoid write-allocate; keep plain stores.

#define CC    3
#define HH    4096
#define WW    4096
#define CHW   (CC * HH * WW)            // 50331648
#define NPAR  12582912                   // C * 512 * 512 * 16
#define NTILE 3072                       // C * 512 * 2 tiles (8 x 2048 each)
#define SMSTRIDE 258                     // 16 ranks * 258 floats (padded)

__device__ float g_p1[NTILE];            // per-CTA sum(eps^2)
__device__ float g_p2[NTILE];            // per-CTA sum(log_std)
__device__ int   g_done = 0;             // completion counter

// zigzag rank within 8x8 block for the first 16 coefficients; -1 = not kept.
__constant__ signed char RANK[64] = {
     0,  2,  3,  9, 10, -1, -1, -1,   // u=0
     1,  4,  8, 11, -1, -1, -1, -1,   // u=1
     5,  7, 12, -1, -1, -1, -1, -1,   // u=2
     6, 13, -1, -1, -1, -1, -1, -1,   // u=3
    14, -1, -1, -1, -1, -1, -1, -1,   // u=4
    15, -1, -1, -1, -1, -1, -1, -1,   // u=5
    -1, -1, -1, -1, -1, -1, -1, -1,   // u=6
    -1, -1, -1, -1, -1, -1, -1, -1    // u=7
};

__global__ __launch_bounds__(256, 8)
void dct_tile_kernel(const float* __restrict__ mean,
                     const float* __restrict__ lstd,
                     const float* __restrict__ eps,
                     float* __restrict__ out, int out_size)
{
    __shared__ float sm[16 * SMSTRIDE];   // sm[rank*258 + blk], 16.5 KB

    const int tile = blockIdx.x;          // 0..3071
    const int c    = tile >> 10;          // tile / 1024
    const int rr   = tile & 1023;
    const int bh   = rr >> 1;             // block-row 0..511
    const int tw   = rr & 1;              // which 2048-col half
    const int tid  = threadIdx.x;

    const int rowbase = (c << 12) + (bh << 3);   // global row of u=0
    float4* out4 = (float4*)out;

    // ---- Phase 0: all-zero rows (u = 6,7), no dependencies ----
    {
        const float4 z = make_float4(0.f, 0.f, 0.f, 0.f);
        #pragma unroll
        for (int k = 12; k < 16; k++) {
            int f    = tid + (k << 8);    // 3072..4095 -> u = 6,7
            int u    = f >> 9;
            int col4 = f & 511;
            out4[(rowbase + u) * 1024 + (tw << 9) + col4] = z;
        }
    }

    // param base for this tile: ((c*512 + bh)*512 + tw*256) * 16 floats
    const int base = ((((c << 9) + bh) << 9) + (tw << 8)) << 4;
    const float4* m4 = (const float4*)(mean + base);
    const float4* l4 = (const float4*)(lstd + base);
    const float4* e4 = (const float4*)(eps  + base);

    float s1 = 0.f, s2 = 0.f;

    // ---- Phase 1: coalesced param load + sample + stage to smem ----
    #pragma unroll
    for (int k = 0; k < 4; k++) {
        int f = tid + (k << 8);           // float4 index, 0..1023
        float4 m = m4[f];
        float4 l = l4[f];
        float4 e = e4[f];
        float4 s;
        s.x = fmaf(__expf(l.x), e.x, m.x);
        s.y = fmaf(__expf(l.y), e.y, m.y);
        s.z = fmaf(__expf(l.z), e.z, m.z);
        s.w = fmaf(__expf(l.w), e.w, m.w);
        s1 = fmaf(e.x, e.x, s1); s1 = fmaf(e.y, e.y, s1);
        s1 = fmaf(e.z, e.z, s1); s1 = fmaf(e.w, e.w, s1);
        s2 += (l.x + l.y) + (l.z + l.w);
        int p = f << 2;                   // param index within tile
        sm[((p + 0) & 15) * SMSTRIDE + ((p + 0) >> 4)] = s.x;
        sm[((p + 1) & 15) * SMSTRIDE + ((p + 1) >> 4)] = s.y;
        sm[((p + 2) & 15) * SMSTRIDE + ((p + 2) >> 4)] = s.z;
        sm[((p + 3) & 15) * SMSTRIDE + ((p + 3) >> 4)] = s.w;
    }
    __syncthreads();

    // ---- Phase 2: coalesced tile store (rows u=0..5) with smem gather ----
    #pragma unroll
    for (int k = 0; k < 12; k++) {
        int f    = tid + (k << 8);        // 0..3071 (u = 0..5)
        int u    = f >> 9;                // row within tile
        int col4 = f & 511;               // float4 col within tile
        int half = col4 & 1;              // v0 = 4*half
        int blk  = col4 >> 1;             // block within tile, 0..255
        int ri   = (u << 3) + (half << 2);
        float4 v;
        int r0 = RANK[ri + 0];
        int r1 = RANK[ri + 1];
        int r2 = RANK[ri + 2];
        int r3 = RANK[ri + 3];
        v.x = (r0 >= 0) ? sm[r0 * SMSTRIDE + blk] : 0.f;
        v.y = (r1 >= 0) ? sm[r1 * SMSTRIDE + blk] : 0.f;
        v.z = (r2 >= 0) ? sm[r2 * SMSTRIDE + blk] : 0.f;
        v.w = (r3 >= 0) ? sm[r3 * SMSTRIDE + blk] : 0.f;
        out4[(rowbase + u) * 1024 + (tw << 9) + col4] = v;
    }

    // ---- Per-CTA reduction: warp shfl -> shared -> partial slot ----
    #pragma unroll
    for (int off = 16; off > 0; off >>= 1) {
        s1 += __shfl_down_sync(0xffffffffu, s1, off);
        s2 += __shfl_down_sync(0xffffffffu, s2, off);
    }
    __shared__ float sh1[8], sh2[8];
    __shared__ int is_last;
    int lane = tid & 31, wrp = tid >> 5;
    if (lane == 0) { sh1[wrp] = s1; sh2[wrp] = s2; }
    __syncthreads();
    if (tid == 0) {
        float t1 = 0.f, t2 = 0.f;
        #pragma unroll
        for (int i = 0; i < 8; i++) { t1 += sh1[i]; t2 += sh2[i]; }
        g_p1[tile] = t1;
        g_p2[tile] = t2;
        __threadfence();                     // make partials visible
        int old = atomicAdd(&g_done, 1);
        is_last = (old == NTILE - 1);
    }
    __syncthreads();

    // ---- Last CTA: final reduction over all 3072 partials ----
    if (is_last) {
        double t1 = 0.0, t2 = 0.0;
        for (int i = tid; i < NTILE; i += 256) {
            t1 += (double)g_p1[i];
            t2 += (double)g_p2[i];
        }
        #pragma unroll
        for (int off = 16; off > 0; off >>= 1) {
            t1 += __shfl_down_sync(0xffffffffu, t1, off);
            t2 += __shfl_down_sync(0xffffffffu, t2, off);
        }
        __shared__ double dh1[8], dh2[8];
        if (lane == 0) { dh1[wrp] = t1; dh2[wrp] = t2; }
        __syncthreads();
        if (tid == 0) {
            double S1 = 0.0, S2 = 0.0;
            #pragma unroll
            for (int i = 0; i < 8; i++) { S1 += dh1[i]; S2 += dh2[i]; }
            const double LOG2PI = 1.8378770664093454836;
            double lp  = -0.5 * (S1 + 2.0 * S2 + (double)NPAR * LOG2PI);
            double ent = (double)NPAR * 0.5 * (1.0 + LOG2PI) + S2;
            if (out_size >= CHW + 2) {
                out[CHW]     = (float)lp;
                out[CHW + 1] = (float)ent;
            }
            g_done = 0;                      // reset for next graph replay
        }
    }
}

extern "C" void kernel_launch(void* const* d_in, const int* in_sizes, int n_in,
                              void* d_out, int out_size)
{
    const float* mean = (const float*)d_in[0];
    const float* lstd = (const float*)d_in[1];
    const float* eps  = (const float*)d_in[2];
    // d_in[3] = flat_idx — unused; index map computed analytically.
    float* out = (float*)d_out;

    dct_tile_kernel<<<NTILE, 256>>>(mean, lstd, eps, out, out_size);
}

// round 8
// speedup vs baseline: 1.0255x; 1.0120x over previous
#include <cuda_runtime.h>
#include <cuda_bf16.h>

// DCTPolicy: out = [coeffs (3*4096*4096 f32), log_prob, entropy]
//
// Persistent-CTA formulation: grid = 1184 (148 SMs x 8 CTAs), each CTA
// strides over 12288 small tiles (8 rows x 512 cols = 64 consecutive 8x8
// blocks = 1024 contiguous params per array). Per tile iteration:
//   - compute samples from the prefetched m/l/e registers, stage into
//     smem[buf] (transposed, padded stride 66 -> conflict-free STS),
//   - ONE __syncthreads (double buffer makes the 2nd bar unnecessary),
//   - PREFETCH next tile's 3x LDG.128 (overlaps the store drain below),
//   - store zero rows (u=6,7) + gather-store rows u=0..5 from smem.
// This removes the 2.59-wave tail quantization of the 3072-CTA version and
// keeps loads outstanding during every store phase (mixed DRAM stream).
//
// Reductions: per-CTA register accumulation across all its tiles -> 1184
// partial slots; last CTA (atomic counter) reduces in double, writes the
// two scalars, resets the counter (graph-replay deterministic).

#define CC    3
#define CHW   50331648                   // 3*4096*4096
#define NPAR  12582912                   // C * 512 * 512 * 16
#define NT    12288                      // tiles: 3 * 512 rows * 8 per row
#define GRID  1184                       // 148 * 8
#define SMSTRIDE 66                      // 64 blocks + 2 pad

__device__ float g_p1[GRID];
__device__ float g_p2[GRID];
__device__ int   g_done = 0;

// zigzag rank within 8x8 block for the first 16 coefficients; -1 = not kept.
__constant__ signed char RANK[64] = {
     0,  2,  3,  9, 10, -1, -1, -1,   // u=0
     1,  4,  8, 11, -1, -1, -1, -1,   // u=1
     5,  7, 12, -1, -1, -1, -1, -1,   // u=2
     6, 13, -1, -1, -1, -1, -1, -1,   // u=3
    14, -1, -1, -1, -1, -1, -1, -1,   // u=4
    15, -1, -1, -1, -1, -1, -1, -1,   // u=5
    -1, -1, -1, -1, -1, -1, -1, -1,   // u=6
    -1, -1, -1, -1, -1, -1, -1, -1    // u=7
};

__global__ __launch_bounds__(256)
void dct_persist_kernel(const float* __restrict__ mean,
                        const float* __restrict__ lstd,
                        const float* __restrict__ eps,
                        float* __restrict__ out, int out_size)
{
    __shared__ float sm[2][16 * SMSTRIDE];   // 2 x 4.22 KB

    const int tid  = threadIdx.x;
    float4* out4 = (float4*)out;

    float s1 = 0.f, s2 = 0.f;

    int tt = blockIdx.x;
    // ---- prologue: load first tile ----
    int base = tt << 10;                  // tile_index * 1024 params
    float4 m = ((const float4*)(mean + base))[tid];
    float4 l = ((const float4*)(lstd + base))[tid];
    float4 e = ((const float4*)(eps  + base))[tid];

    int buf = 0;
    while (true) {
        const int cur = tt;
        tt += GRID;
        const bool hasnext = (tt < NT);

        // ---- compute + stage current tile into sm[buf] ----
        {
            float4 s;
            s.x = fmaf(__expf(l.x), e.x, m.x);
            s.y = fmaf(__expf(l.y), e.y, m.y);
            s.z = fmaf(__expf(l.z), e.z, m.z);
            s.w = fmaf(__expf(l.w), e.w, m.w);
            s1 = fmaf(e.x, e.x, s1); s1 = fmaf(e.y, e.y, s1);
            s1 = fmaf(e.z, e.z, s1); s1 = fmaf(e.w, e.w, s1);
            s2 += (l.x + l.y) + (l.z + l.w);
            int p = tid << 2;             // param index within tile
            float* b = sm[buf];
            b[((p + 0) & 15) * SMSTRIDE + ((p + 0) >> 4)] = s.x;
            b[((p + 1) & 15) * SMSTRIDE + ((p + 1) >> 4)] = s.y;
            b[((p + 2) & 15) * SMSTRIDE + ((p + 2) >> 4)] = s.z;
            b[((p + 3) & 15) * SMSTRIDE + ((p + 3) >> 4)] = s.w;
        }
        __syncthreads();

        // ---- prefetch next tile (overlaps the store drain below) ----
        if (hasnext) {
            int nbase = tt << 10;
            m = ((const float4*)(mean + nbase))[tid];
            l = ((const float4*)(lstd + nbase))[tid];
            e = ((const float4*)(eps  + nbase))[tid];
        }

        // ---- current tile output coordinates ----
        // cur: c = cur/4096, bh = (cur%4096)/8, tq = cur%8
        const int c    = cur >> 12;
        const int rem  = cur & 4095;
        const int bh   = rem >> 3;
        const int tq   = rem & 7;
        const int rowbase  = (c << 12) + (bh << 3);
        const int colbase4 = tq << 7;     // float4 col offset, 128 per tile

        // zero rows u = 6,7 (k = 3), independent of smem
        {
            int f = tid + 768;            // 768..1023 -> u in {6,7}
            int u = f >> 7;
            int col4 = f & 127;
            out4[(rowbase + u) * 1024 + colbase4 + col4] =
                make_float4(0.f, 0.f, 0.f, 0.f);
        }

        // gather-store rows u = 0..5 (k = 0..2)
        const float* b = sm[buf];
        #pragma unroll
        for (int k = 0; k < 3; k++) {
            int f    = tid + (k << 8);    // 0..767
            int u    = f >> 7;            // 128 float4 per row
            int col4 = f & 127;
            int half = col4 & 1;
            int blk  = col4 >> 1;         // 0..63
            int ri   = (u << 3) + (half << 2);
            float4 v;
            int r0 = RANK[ri + 0];
            int r1 = RANK[ri + 1];
            int r2 = RANK[ri + 2];
            int r3 = RANK[ri + 3];
            v.x = (r0 >= 0) ? b[r0 * SMSTRIDE + blk] : 0.f;
            v.y = (r1 >= 0) ? b[r1 * SMSTRIDE + blk] : 0.f;
            v.z = (r2 >= 0) ? b[r2 * SMSTRIDE + blk] : 0.f;
            v.w = (r3 >= 0) ? b[r3 * SMSTRIDE + blk] : 0.f;
            out4[(rowbase + u) * 1024 + colbase4 + col4] = v;
        }

        buf ^= 1;
        if (!hasnext) break;
    }

    // ---- per-CTA reduction: warp shfl -> shared -> partial slot ----
    #pragma unroll
    for (int off = 16; off > 0; off >>= 1) {
        s1 += __shfl_down_sync(0xffffffffu, s1, off);
        s2 += __shfl_down_sync(0xffffffffu, s2, off);
    }
    __shared__ float sh1[8], sh2[8];
    __shared__ int is_last;
    int lane = tid & 31, wrp = tid >> 5;
    if (lane == 0) { sh1[wrp] = s1; sh2[wrp] = s2; }
    __syncthreads();
    if (tid == 0) {
        float t1 = 0.f, t2 = 0.f;
        #pragma unroll
        for (int i = 0; i < 8; i++) { t1 += sh1[i]; t2 += sh2[i]; }
        g_p1[blockIdx.x] = t1;
        g_p2[blockIdx.x] = t2;
        __threadfence();
        int old = atomicAdd(&g_done, 1);
        is_last = (old == GRID - 1);
    }
    __syncthreads();

    // ---- last CTA: final reduction over all 1184 partials ----
    if (is_last) {
        double t1 = 0.0, t2 = 0.0;
        for (int i = tid; i < GRID; i += 256) {
            t1 += (double)g_p1[i];
            t2 += (double)g_p2[i];
        }
        #pragma unroll
        for (int off = 16; off > 0; off >>= 1) {
            t1 += __shfl_down_sync(0xffffffffu, t1, off);
            t2 += __shfl_down_sync(0xffffffffu, t2, off);
        }
        __shared__ double dh1[8], dh2[8];
        if (lane == 0) { dh1[wrp] = t1; dh2[wrp] = t2; }
        __syncthreads();
        if (tid == 0) {
            double S1 = 0.0, S2 = 0.0;
            #pragma unroll
            for (int i = 0; i < 8; i++) { S1 += dh1[i]; S2 += dh2[i]; }
            const double LOG2PI = 1.8378770664093454836;
            double lp  = -0.5 * (S1 + 2.0 * S2 + (double)NPAR * LOG2PI);
            double ent = (double)NPAR * 0.5 * (1.0 + LOG2PI) + S2;
            if (out_size >= CHW + 2) {
                out[CHW]     = (float)lp;
                out[CHW + 1] = (float)ent;
            }
            g_done = 0;                   // reset for next graph replay
        }
    }
}

extern "C" void kernel_launch(void* const* d_in, const int* in_sizes, int n_in,
                              void* d_out, int out_size)
{
    const float* mean = (const float*)d_in[0];
    const float* lstd = (const float*)d_in[1];
    const float* eps  = (const float*)d_in[2];
    // d_in[3] = flat_idx — unused; index map computed analytically.
    float* out = (float*)d_out;

    dct_persist_kernel<<<GRID, 256>>>(mean, lstd, eps, out, out_size);
}